// round 16
// baseline (speedup 1.0000x reference)
#include <cuda_runtime.h>
#include <cuda_bf16.h>

#define MAXN 100000
#define MAXE 1000000
#define MAXG 1024
#define SCAN_T 512

// ---------------- scratch (device globals: no allocation allowed) ----------------
__device__ int   g_idx64;
__device__ int   g_degcnt[MAXN];
__device__ int   g_cursor[MAXN];
__device__ int   g_rowptr[MAXN + 1];
__device__ int   g_bsum[256];
__device__ int   g_col[MAXE];
__device__ float g_dinv[MAXN];
__device__ float g_selfc[MAXN];
__device__ float g_y[MAXN * 128];   // layer-2 aggregation output
__device__ float g_h[MAXN * 128];   // layer-1 output (h1)
__device__ float g_psum[MAXG * 128];
__device__ float g_gcnt[MAXG];
// bf16 hi/lo split of W1/W2, TRANSPOSED to [n][k] (B operand, K-major)
__device__ __nv_bfloat16 g_w1hi[64 * 128],  g_w1lo[64 * 128];
__device__ __nv_bfloat16 g_w2hi[128 * 128], g_w2lo[128 * 128];

// ---------------- generic helpers ----------------
__device__ __forceinline__ void vfma(float4& a, float4 v, float s) {
    a.x = fmaf(v.x, s, a.x); a.y = fmaf(v.y, s, a.y);
    a.z = fmaf(v.z, s, a.z); a.w = fmaf(v.w, s, a.w);
}
__device__ __forceinline__ void vfma(float2& a, float2 v, float s) {
    a.x = fmaf(v.x, s, a.x); a.y = fmaf(v.y, s, a.y);
}
__device__ __forceinline__ float4 vscale(float4 v, float s) { return make_float4(v.x*s, v.y*s, v.z*s, v.w*s); }
__device__ __forceinline__ float2 vscale(float2 v, float s) { return make_float2(v.x*s, v.y*s); }

__device__ __forceinline__ int idx_at(const void* p, int i) {
    return g_idx64 ? (int)((const long long*)p)[i] : ((const int*)p)[i];
}

__device__ __forceinline__ unsigned s2u(const void* p) {
    unsigned a;
    asm("{ .reg .u64 t; cvta.to.shared.u64 t, %1; cvt.u32.u64 %0, t; }" : "=r"(a) : "l"(p));
    return a;
}

__device__ __forceinline__ unsigned packbf(__nv_bfloat16 a, __nv_bfloat16 b) {
    unsigned short ua = *(unsigned short*)&a, ub = *(unsigned short*)&b;
    return (unsigned)ua | ((unsigned)ub << 16);
}
__device__ __forceinline__ void split2(float f0, float f1, unsigned& hi, unsigned& lo) {
    __nv_bfloat16 h0 = __float2bfloat16(f0), h1 = __float2bfloat16(f1);
    float r0 = f0 - __bfloat162float(h0), r1 = f1 - __bfloat162float(h1);
    hi = packbf(h0, h1);
    lo = packbf(__float2bfloat16(r0), __float2bfloat16(r1));
}

// ---------------- mma.sync helpers ----------------
#define LDM4(r, addr) \
    asm volatile("ldmatrix.sync.aligned.m8n8.x4.shared.b16 {%0,%1,%2,%3}, [%4];" \
        : "=r"((r)[0]), "=r"((r)[1]), "=r"((r)[2]), "=r"((r)[3]) : "r"(addr))

#define MMA_BF16(c, a, b0, b1) \
    asm volatile("mma.sync.aligned.m16n8k16.row.col.f32.bf16.bf16.f32 " \
        "{%0,%1,%2,%3}, {%4,%5,%6,%7}, {%8,%9}, {%0,%1,%2,%3};" \
        : "+f"((c)[0]), "+f"((c)[1]), "+f"((c)[2]), "+f"((c)[3]) \
        : "r"((a)[0]), "r"((a)[1]), "r"((a)[2]), "r"((a)[3]), "r"(b0), "r"(b1))

// ---------------- k_setup: detect dtype + zero psum/gcnt + W split ----------------
__global__ void k_setup(const unsigned* __restrict__ ei,
                        const float* __restrict__ W1, const float* __restrict__ W2, int G) {
    int i = blockIdx.x * 256 + threadIdx.x;   // grid: 256 x 256 = 65536
    if (i == 0) {
        unsigned o = ei[1] | ei[3] | ei[5] | ei[7] | ei[9] | ei[11] | ei[13] | ei[15];
        g_idx64 = (o == 0u) ? 1 : 0;
    }
    if (i < G * 128) g_psum[i] = 0.f;
    if (i < G) g_gcnt[i] = 0.f;
    if (i < 64 * 128) {
        int k = i >> 7, n = i & 127;
        float v = W1[i];
        __nv_bfloat16 h = __float2bfloat16(v);
        g_w1hi[n * 64 + k] = h;
        g_w1lo[n * 64 + k] = __float2bfloat16(v - __bfloat162float(h));
    }
    if (i < 128 * 128) {
        int k = i >> 7, n = i & 127;
        float v = W2[i];
        __nv_bfloat16 h = __float2bfloat16(v);
        g_w2hi[n * 128 + k] = h;
        g_w2lo[n * 128 + k] = __float2bfloat16(v - __bfloat162float(h));
    }
}

// ---------------- zero deg/cursor + count nodes per graph ----------------
__global__ void k_zero(const void* __restrict__ batch, int N) {
    int i = blockIdx.x * blockDim.x + threadIdx.x;
    if (i < N) {
        g_degcnt[i] = 0;
        g_cursor[i] = 0;
        atomicAdd(&g_gcnt[idx_at(batch, i)], 1.f);
    }
}

// ---------------- edge counting ----------------
__global__ void k_count(const void* __restrict__ ei, int E) {
    int e = blockIdx.x * blockDim.x + threadIdx.x;
    if (e < E) atomicAdd(&g_degcnt[idx_at(ei, E + e)], 1);
}

// ---------------- scan phase 1: per-block sums ----------------
__global__ void k_scan1(int N) {
    __shared__ int ss[SCAN_T];
    int tid = threadIdx.x;
    int i = blockIdx.x * SCAN_T + tid;
    ss[tid] = (i < N) ? g_degcnt[i] : 0;
    __syncthreads();
#pragma unroll
    for (int off = SCAN_T / 2; off > 0; off >>= 1) {
        if (tid < off) ss[tid] += ss[tid + off];
        __syncthreads();
    }
    if (tid == 0) g_bsum[blockIdx.x] = ss[0];
}

// ---------------- scan phases 2+3 merged ----------------
__global__ void k_scan23(int nb, int N) {
    __shared__ int ss[SCAN_T];
    __shared__ int ss2[256];
    int tid = threadIdx.x;
    if (tid < 256) ss2[tid] = (tid < nb) ? g_bsum[tid] : 0;
    __syncthreads();
#pragma unroll
    for (int off = 1; off < 256; off <<= 1) {
        int t = 0;
        if (tid < 256 && tid >= off) t = ss2[tid - off];
        __syncthreads();
        if (tid < 256) ss2[tid] += t;
        __syncthreads();
    }
    int bid = blockIdx.x;
    int prefix = (bid == 0) ? 0 : ss2[bid - 1];
    int i = bid * SCAN_T + tid;
    int v = (i < N) ? g_degcnt[i] : 0;
    ss[tid] = v;
    __syncthreads();
#pragma unroll
    for (int off = 1; off < SCAN_T; off <<= 1) {
        int t = (tid >= off) ? ss[tid - off] : 0;
        __syncthreads();
        ss[tid] += t;
        __syncthreads();
    }
    if (i < N) {
        g_rowptr[i] = prefix + ss[tid] - v;
        float d = (float)v + 1.0f;
        g_dinv[i]  = rsqrtf(d);
        g_selfc[i] = 1.0f / d;
    }
    if (bid == nb - 1 && tid == SCAN_T - 1) g_rowptr[N] = ss2[nb - 1];
}

__global__ void k_fill(const void* __restrict__ ei, int E) {
    int e = blockIdx.x * blockDim.x + threadIdx.x;
    if (e < E) {
        int s = idx_at(ei, e);
        int d = idx_at(ei, E + e);
        int pos = g_rowptr[d] + atomicAdd(&g_cursor[d], 1);
        g_col[pos] = s;
    }
}

// ---------------- layer-2 aggregation ----------------
template <typename VecT>
__global__ void k_agg(int N) {
    int t = blockIdx.x * blockDim.x + threadIdx.x;
    int node = t >> 5;
    int lane = t & 31;
    if (node >= N) return;
    const VecT* __restrict__ xv = (const VecT*)g_h;
    VecT a = vscale(xv[node * 32 + lane], g_selfc[node]);
    float di = g_dinv[node];
    int p = g_rowptr[node];
    int e = g_rowptr[node + 1];
    for (; p + 4 <= e; p += 4) {
        int s0 = __ldg(&g_col[p]);
        int s1 = __ldg(&g_col[p + 1]);
        int s2 = __ldg(&g_col[p + 2]);
        int s3 = __ldg(&g_col[p + 3]);
        float w0 = di * __ldg(&g_dinv[s0]);
        float w1 = di * __ldg(&g_dinv[s1]);
        float w2 = di * __ldg(&g_dinv[s2]);
        float w3 = di * __ldg(&g_dinv[s3]);
        VecT v0 = xv[s0 * 32 + lane];
        VecT v1 = xv[s1 * 32 + lane];
        VecT v2 = xv[s2 * 32 + lane];
        VecT v3 = xv[s3 * 32 + lane];
        vfma(a, v0, w0);
        vfma(a, v1, w1);
        vfma(a, v2, w2);
        vfma(a, v3, w3);
    }
    for (; p < e; p++) {
        int s0 = __ldg(&g_col[p]);
        vfma(a, xv[s0 * 32 + lane], di * __ldg(&g_dinv[s0]));
    }
    ((VecT*)g_y)[node * 32 + lane] = a;
}

// ---------------- layer 1 FUSED: aggregate x (K=64) + GEMM + relu -> g_h ----------------
__global__ void __launch_bounds__(256) k_fused64(const float* __restrict__ x,
                                                 const float* __restrict__ bias, int N) {
    __shared__ __nv_bfloat16 a_hi[64 * 72], a_lo[64 * 72];    // pitch 72
    __shared__ __nv_bfloat16 b_hi[128 * 40], b_lo[128 * 40];  // pitch 40

    const int tid  = threadIdx.x;
    const int lane = tid & 31;
    const int wid  = tid >> 5;
    const int row0 = blockIdx.x * 64;

    // ---- aggregation: warp handles 8 nodes ----
    const float2* __restrict__ xv = (const float2*)x;
    for (int j = 0; j < 8; j++) {
        int node = row0 + wid * 8 + j;
        float2 a = make_float2(0.f, 0.f);
        if (node < N) {
            a = vscale(xv[node * 32 + lane], g_selfc[node]);
            float di = g_dinv[node];
            int p = g_rowptr[node];
            int e = g_rowptr[node + 1];
            for (; p + 4 <= e; p += 4) {
                int s0 = __ldg(&g_col[p]);
                int s1 = __ldg(&g_col[p + 1]);
                int s2 = __ldg(&g_col[p + 2]);
                int s3 = __ldg(&g_col[p + 3]);
                float w0 = di * __ldg(&g_dinv[s0]);
                float w1 = di * __ldg(&g_dinv[s1]);
                float w2 = di * __ldg(&g_dinv[s2]);
                float w3 = di * __ldg(&g_dinv[s3]);
                float2 v0 = xv[s0 * 32 + lane];
                float2 v1 = xv[s1 * 32 + lane];
                float2 v2 = xv[s2 * 32 + lane];
                float2 v3 = xv[s3 * 32 + lane];
                vfma(a, v0, w0);
                vfma(a, v1, w1);
                vfma(a, v2, w2);
                vfma(a, v3, w3);
            }
            for (; p < e; p++) {
                int s0 = __ldg(&g_col[p]);
                vfma(a, xv[s0 * 32 + lane], di * __ldg(&g_dinv[s0]));
            }
        }
        unsigned h, l;
        split2(a.x, a.y, h, l);
        ((unsigned*)a_hi)[(wid * 8 + j) * 36 + lane] = h;
        ((unsigned*)a_lo)[(wid * 8 + j) * 36 + lane] = l;
    }

    // ---- GEMM ----
    const int mrow0 = (wid >> 1) * 16;
    const int ncol0 = (wid & 1) * 64;

    float acc[8][4];
#pragma unroll
    for (int nt = 0; nt < 8; nt++)
#pragma unroll
        for (int j = 0; j < 4; j++) acc[nt][j] = 0.f;

    const unsigned a_hi_u = s2u(a_hi), a_lo_u = s2u(a_lo);
    const unsigned b_hi_u = s2u(b_hi), b_lo_u = s2u(b_lo);
    const int r = tid >> 1, half = tid & 1;
    const int lr = lane & 15, lc = lane >> 4;

    for (int kc = 0; kc < 64; kc += 32) {
        __syncthreads();
        // stage B chunk: each thread covers 16 bf16 -> TWO uint4 loads (bug fix)
        {
            const uint4* sh = (const uint4*)(g_w1hi + r * 64 + kc + half * 16);
            const uint4* sl = (const uint4*)(g_w1lo + r * 64 + kc + half * 16);
            unsigned dsto = (unsigned)(r * 40 + half * 16) * 2;
            *(uint4*)((char*)b_hi + dsto)      = sh[0];
            *(uint4*)((char*)b_hi + dsto + 16) = sh[1];
            *(uint4*)((char*)b_lo + dsto)      = sl[0];
            *(uint4*)((char*)b_lo + dsto + 16) = sl[1];
        }
        __syncthreads();

#pragma unroll
        for (int ks = 0; ks < 32; ks += 16) {
            unsigned ah[4], al[4];
            unsigned ao = (unsigned)((mrow0 + lr) * 72 + kc + ks + lc * 8) * 2;
            LDM4(ah, a_hi_u + ao);
            LDM4(al, a_lo_u + ao);
#pragma unroll
            for (int np = 0; np < 4; np++) {
                unsigned bo = (unsigned)((ncol0 + np * 16 + lr) * 40 + ks + lc * 8) * 2;
                unsigned bh[4], bl[4];
                LDM4(bh, b_hi_u + bo);
                LDM4(bl, b_lo_u + bo);
#pragma unroll
                for (int sub = 0; sub < 2; sub++) {
                    int nt = 2 * np + sub;
                    MMA_BF16(acc[nt], ah, bh[sub], bh[sub + 2]);
                    MMA_BF16(acc[nt], ah, bl[sub], bl[sub + 2]);
                    MMA_BF16(acc[nt], al, bh[sub], bh[sub + 2]);
                }
            }
        }
    }

    // ---- epilogue: bias + relu -> g_h ----
    const int tq  = lane >> 2;
    const int tc2 = (lane & 3) * 2;
    int rowa = row0 + mrow0 + tq;
    int rowb = rowa + 8;
#pragma unroll
    for (int nt = 0; nt < 8; nt++) {
        int col = ncol0 + nt * 8 + tc2;
        float b0 = __ldg(&bias[col]), b1 = __ldg(&bias[col + 1]);
        const float* c = acc[nt];
        if (rowa < N)
            *(float2*)(g_h + (size_t)rowa * 128 + col) =
                make_float2(fmaxf(c[0] + b0, 0.f), fmaxf(c[1] + b1, 0.f));
        if (rowb < N)
            *(float2*)(g_h + (size_t)rowb * 128 + col) =
                make_float2(fmaxf(c[2] + b0, 0.f), fmaxf(c[3] + b1, 0.f));
    }
}

// ---------------- layer-2 GEMM + fused pooling ----------------
__global__ void __launch_bounds__(256) k_mma128(const float* __restrict__ bias,
                                                const void* __restrict__ batch, int N) {
    __shared__ __align__(16) char smraw[40960];
    __nv_bfloat16* a_hi = (__nv_bfloat16*)(smraw);
    __nv_bfloat16* a_lo = (__nv_bfloat16*)(smraw + 10240);
    __nv_bfloat16* b_hi = (__nv_bfloat16*)(smraw + 20480);
    __nv_bfloat16* b_lo = (__nv_bfloat16*)(smraw + 30720);
    float* ps = (float*)smraw;   // [64][132] pool staging

    const int tid  = threadIdx.x;
    const int lane = tid & 31;
    const int wid  = tid >> 5;
    const int row0 = blockIdx.x * 128;
    const int mrow0 = (wid >> 1) * 32;
    const int ncol0 = (wid & 1) * 64;

    float acc[2][8][4];
#pragma unroll
    for (int mt = 0; mt < 2; mt++)
#pragma unroll
        for (int nt = 0; nt < 8; nt++)
#pragma unroll
            for (int j = 0; j < 4; j++) acc[mt][nt][j] = 0.f;

    const unsigned a_hi_u = s2u(a_hi), a_lo_u = s2u(a_lo);
    const unsigned b_hi_u = s2u(b_hi), b_lo_u = s2u(b_lo);
    const int r = tid >> 1, half = tid & 1;

    for (int kc = 0; kc < 128; kc += 32) {
        __syncthreads();
        // stage A
        {
            int rowA = row0 + r;
            unsigned dsto = (unsigned)(r * 40 + half * 16) * 2;
            if (rowA < N) {
                const float4* src = (const float4*)(g_y + (size_t)rowA * 128 + kc + half * 16);
#pragma unroll
                for (int j = 0; j < 4; j++) {
                    float4 v = src[j];
                    unsigned h0, l0, h1, l1;
                    split2(v.x, v.y, h0, l0);
                    split2(v.z, v.w, h1, l1);
                    *(uint2*)((char*)a_hi + dsto + j * 8) = make_uint2(h0, h1);
                    *(uint2*)((char*)a_lo + dsto + j * 8) = make_uint2(l0, l1);
                }
            } else {
#pragma unroll
                for (int j = 0; j < 4; j++) {
                    *(uint2*)((char*)a_hi + dsto + j * 8) = make_uint2(0u, 0u);
                    *(uint2*)((char*)a_lo + dsto + j * 8) = make_uint2(0u, 0u);
                }
            }
        }
        // stage B: TWO uint4 loads per thread (bug fix)
        {
            const uint4* sh = (const uint4*)(g_w2hi + r * 128 + kc + half * 16);
            const uint4* sl = (const uint4*)(g_w2lo + r * 128 + kc + half * 16);
            unsigned dsto = (unsigned)(r * 40 + half * 16) * 2;
            *(uint4*)((char*)b_hi + dsto)      = sh[0];
            *(uint4*)((char*)b_hi + dsto + 16) = sh[1];
            *(uint4*)((char*)b_lo + dsto)      = sl[0];
            *(uint4*)((char*)b_lo + dsto + 16) = sl[1];
        }
        __syncthreads();

        const int lr = lane & 15, lc = lane >> 4;
#pragma unroll
        for (int ks = 0; ks < 32; ks += 16) {
            unsigned ah[2][4], al[2][4];
#pragma unroll
            for (int mt = 0; mt < 2; mt++) {
                unsigned ao = (unsigned)((mrow0 + mt * 16 + lr) * 40 + ks + lc * 8) * 2;
                LDM4(ah[mt], a_hi_u + ao);
                LDM4(al[mt], a_lo_u + ao);
            }
#pragma unroll
            for (int np = 0; np < 4; np++) {
                unsigned bo = (unsigned)((ncol0 + np * 16 + lr) * 40 + ks + lc * 8) * 2;
                unsigned bh[4], bl[4];
                LDM4(bh, b_hi_u + bo);
                LDM4(bl, b_lo_u + bo);
#pragma unroll
                for (int sub = 0; sub < 2; sub++) {
                    int nt = 2 * np + sub;
#pragma unroll
                    for (int mt = 0; mt < 2; mt++) {
                        MMA_BF16(acc[mt][nt], ah[mt], bh[sub], bh[sub + 2]);
                        MMA_BF16(acc[mt][nt], ah[mt], bl[sub], bl[sub + 2]);
                        MMA_BF16(acc[mt][nt], al[mt], bh[sub], bh[sub + 2]);
                    }
                }
            }
        }
    }

    const int tq  = lane >> 2;
    const int tc2 = (lane & 3) * 2;
#pragma unroll
    for (int P = 0; P < 2; P++) {
        __syncthreads();
        if ((mrow0 >> 6) == P) {
            int baseR = mrow0 & 63;
#pragma unroll
            for (int mt = 0; mt < 2; mt++) {
                int ra = baseR + mt * 16 + tq;
                int rb = ra + 8;
#pragma unroll
                for (int nt = 0; nt < 8; nt++) {
                    int col = ncol0 + nt * 8 + tc2;
                    float b0 = __ldg(&bias[col]), b1 = __ldg(&bias[col + 1]);
                    const float* c = acc[mt][nt];
                    ps[ra * 132 + col]     = fmaxf(c[0] + b0, 0.f);
                    ps[ra * 132 + col + 1] = fmaxf(c[1] + b1, 0.f);
                    ps[rb * 132 + col]     = fmaxf(c[2] + b0, 0.f);
                    ps[rb * 132 + col + 1] = fmaxf(c[3] + b1, 0.f);
                }
            }
        }
        __syncthreads();
        int c  = tid & 127;
        int rh = tid >> 7;
        int curg = -1;
        float acc2 = 0.f;
        for (int rr = rh * 32; rr < rh * 32 + 32; rr++) {
            int row = row0 + P * 64 + rr;
            if (row >= N) break;
            int g = idx_at(batch, row);
            if (g != curg) {
                if (curg >= 0) atomicAdd(&g_psum[curg * 128 + c], acc2);
                curg = g; acc2 = 0.f;
            }
            acc2 += ps[rr * 132 + c];
        }
        if (curg >= 0) atomicAdd(&g_psum[curg * 128 + c], acc2);
    }
}

// ---------------- final FC (128 -> 2) + softmax ----------------
__global__ void k_fc(const float* __restrict__ Wfc, const float* __restrict__ bfc,
                     float* __restrict__ out, int G) {
    int g = blockIdx.x * blockDim.x + threadIdx.x;
    if (g >= G) return;
    float inv = 1.0f / fmaxf(g_gcnt[g], 1.0f);
    float l0 = bfc[0], l1 = bfc[1];
#pragma unroll 8
    for (int c = 0; c < 128; c++) {
        float p = g_psum[g * 128 + c] * inv;
        l0 = fmaf(p, Wfc[2 * c + 0], l0);
        l1 = fmaf(p, Wfc[2 * c + 1], l1);
    }
    float m = fmaxf(l0, l1);
    float e0 = __expf(l0 - m), e1 = __expf(l1 - m);
    float s = e0 + e1;
    out[2 * g + 0] = e0 / s;
    out[2 * g + 1] = e1 / s;
}

// ---------------- launch: ONLY kernel launches ----------------
extern "C" void kernel_launch(void* const* d_in, const int* in_sizes, int n_in,
                              void* d_out, int out_size) {
    const float* x     = (const float*)d_in[0];
    const void*  ei    = d_in[1];
    const void*  batch = d_in[2];

    const float *W1 = 0, *b1 = 0, *W2 = 0, *b2 = 0, *Wfc = 0, *bfc = 0;
    for (int i = 3; i < n_in; i++) {
        int s = in_sizes[i];
        const float* p = (const float*)d_in[i];
        if      (s == 8192)  W1 = p;
        else if (s == 16384) W2 = p;
        else if (s == 256)   Wfc = p;
        else if (s == 2)     bfc = p;
        else if (s == 128)   { if (!b1) b1 = p; else b2 = p; }
    }

    int N = in_sizes[2];
    int E = in_sizes[1] / 2;
    int G = out_size / 2;

    k_setup<<<256, 256>>>((const unsigned*)ei, W1, W2, G);
    k_zero<<<(N + 255) / 256, 256>>>(batch, N);
    k_count<<<(E + 255) / 256, 256>>>(ei, E);
    int nb = (N + SCAN_T - 1) / SCAN_T;
    k_scan1<<<nb, SCAN_T>>>(N);
    k_scan23<<<nb, SCAN_T>>>(nb, N);
    k_fill<<<(E + 255) / 256, 256>>>(ei, E);

    // layer 1 fused: h1 = relu((A_hat x) W1 + b1)
    k_fused64<<<(N + 63) / 64, 256>>>(x, b1, N);

    // layer 2: g_y = A_hat h1; pooled relu(g_y W2 + b2) -> g_psum
    k_agg<float4><<<(N * 32 + 255) / 256, 256>>>(N);
    k_mma128<<<(N + 127) / 128, 256>>>(b2, batch, N);

    // FC + softmax
    k_fc<<<(G + 127) / 128, 128>>>(Wfc, bfc, (float*)d_out, G);
}

// round 17
// speedup vs baseline: 1.0852x; 1.0852x over previous
#include <cuda_runtime.h>
#include <cuda_bf16.h>

#define MAXN 100000
#define MAXE 1000000
#define MAXG 1024
#define SCAN_T 512

// ---------------- scratch (device globals: no allocation allowed) ----------------
__device__ int   g_idx64;
__device__ int   g_degcnt[MAXN];
__device__ int   g_cursor[MAXN];
__device__ int   g_rowptr[MAXN + 1];
__device__ int   g_bsum[256];
__device__ int   g_col[MAXE];
__device__ float g_dinv[MAXN];
__device__ float g_selfc[MAXN];
__device__ float g_y[MAXN * 128];   // aggregation output (GEMM input)
__device__ float g_h[MAXN * 128];   // layer-1 output (h1)
__device__ float g_psum[MAXG * 128];
__device__ float g_gcnt[MAXG];
// bf16 hi/lo split of W1/W2, TRANSPOSED to [n][k] (B operand, K-major)
__device__ __nv_bfloat16 g_w1hi[64 * 128],  g_w1lo[64 * 128];
__device__ __nv_bfloat16 g_w2hi[128 * 128], g_w2lo[128 * 128];

// ---------------- generic helpers ----------------
__device__ __forceinline__ void vfma(float4& a, float4 v, float s) {
    a.x = fmaf(v.x, s, a.x); a.y = fmaf(v.y, s, a.y);
    a.z = fmaf(v.z, s, a.z); a.w = fmaf(v.w, s, a.w);
}
__device__ __forceinline__ void vfma(float2& a, float2 v, float s) {
    a.x = fmaf(v.x, s, a.x); a.y = fmaf(v.y, s, a.y);
}
__device__ __forceinline__ float4 vscale(float4 v, float s) { return make_float4(v.x*s, v.y*s, v.z*s, v.w*s); }
__device__ __forceinline__ float2 vscale(float2 v, float s) { return make_float2(v.x*s, v.y*s); }

__device__ __forceinline__ int idx_at(const void* p, int i) {
    return g_idx64 ? (int)((const long long*)p)[i] : ((const int*)p)[i];
}

__device__ __forceinline__ unsigned s2u(const void* p) {
    unsigned a;
    asm("{ .reg .u64 t; cvta.to.shared.u64 t, %1; cvt.u32.u64 %0, t; }" : "=r"(a) : "l"(p));
    return a;
}

__device__ __forceinline__ unsigned packbf(__nv_bfloat16 a, __nv_bfloat16 b) {
    unsigned short ua = *(unsigned short*)&a, ub = *(unsigned short*)&b;
    return (unsigned)ua | ((unsigned)ub << 16);
}
__device__ __forceinline__ void split2(float f0, float f1, unsigned& hi, unsigned& lo) {
    __nv_bfloat16 h0 = __float2bfloat16(f0), h1 = __float2bfloat16(f1);
    float r0 = f0 - __bfloat162float(h0), r1 = f1 - __bfloat162float(h1);
    hi = packbf(h0, h1);
    lo = packbf(__float2bfloat16(r0), __float2bfloat16(r1));
}

// ---------------- mma.sync helpers ----------------
#define LDM4(r, addr) \
    asm volatile("ldmatrix.sync.aligned.m8n8.x4.shared.b16 {%0,%1,%2,%3}, [%4];" \
        : "=r"((r)[0]), "=r"((r)[1]), "=r"((r)[2]), "=r"((r)[3]) : "r"(addr))

#define MMA_BF16(c, a, b0, b1) \
    asm volatile("mma.sync.aligned.m16n8k16.row.col.f32.bf16.bf16.f32 " \
        "{%0,%1,%2,%3}, {%4,%5,%6,%7}, {%8,%9}, {%0,%1,%2,%3};" \
        : "+f"((c)[0]), "+f"((c)[1]), "+f"((c)[2]), "+f"((c)[3]) \
        : "r"((a)[0]), "r"((a)[1]), "r"((a)[2]), "r"((a)[3]), "r"(b0), "r"(b1))

// ---------------- k_setup: detect dtype + zero psum/gcnt + W split ----------------
__global__ void k_setup(const unsigned* __restrict__ ei,
                        const float* __restrict__ W1, const float* __restrict__ W2, int G) {
    int i = blockIdx.x * 256 + threadIdx.x;   // grid: 256 x 256 = 65536
    if (i == 0) {
        unsigned o = ei[1] | ei[3] | ei[5] | ei[7] | ei[9] | ei[11] | ei[13] | ei[15];
        g_idx64 = (o == 0u) ? 1 : 0;
    }
    if (i < G * 128) g_psum[i] = 0.f;
    if (i < G) g_gcnt[i] = 0.f;
    if (i < 64 * 128) {
        int k = i >> 7, n = i & 127;
        float v = W1[i];
        __nv_bfloat16 h = __float2bfloat16(v);
        g_w1hi[n * 64 + k] = h;
        g_w1lo[n * 64 + k] = __float2bfloat16(v - __bfloat162float(h));
    }
    if (i < 128 * 128) {
        int k = i >> 7, n = i & 127;
        float v = W2[i];
        __nv_bfloat16 h = __float2bfloat16(v);
        g_w2hi[n * 128 + k] = h;
        g_w2lo[n * 128 + k] = __float2bfloat16(v - __bfloat162float(h));
    }
}

// ---------------- zero deg/cursor + count nodes per graph ----------------
__global__ void k_zero(const void* __restrict__ batch, int N) {
    int i = blockIdx.x * blockDim.x + threadIdx.x;
    if (i < N) {
        g_degcnt[i] = 0;
        g_cursor[i] = 0;
        atomicAdd(&g_gcnt[idx_at(batch, i)], 1.f);
    }
}

// ---------------- edge counting ----------------
__global__ void k_count(const void* __restrict__ ei, int E) {
    int e = blockIdx.x * blockDim.x + threadIdx.x;
    if (e < E) atomicAdd(&g_degcnt[idx_at(ei, E + e)], 1);
}

// ---------------- scan phase 1: per-block sums ----------------
__global__ void k_scan1(int N) {
    __shared__ int ss[SCAN_T];
    int tid = threadIdx.x;
    int i = blockIdx.x * SCAN_T + tid;
    ss[tid] = (i < N) ? g_degcnt[i] : 0;
    __syncthreads();
#pragma unroll
    for (int off = SCAN_T / 2; off > 0; off >>= 1) {
        if (tid < off) ss[tid] += ss[tid + off];
        __syncthreads();
    }
    if (tid == 0) g_bsum[blockIdx.x] = ss[0];
}

// ---------------- scan phases 2+3 merged ----------------
__global__ void k_scan23(int nb, int N) {
    __shared__ int ss[SCAN_T];
    __shared__ int ss2[256];
    int tid = threadIdx.x;
    if (tid < 256) ss2[tid] = (tid < nb) ? g_bsum[tid] : 0;
    __syncthreads();
#pragma unroll
    for (int off = 1; off < 256; off <<= 1) {
        int t = 0;
        if (tid < 256 && tid >= off) t = ss2[tid - off];
        __syncthreads();
        if (tid < 256) ss2[tid] += t;
        __syncthreads();
    }
    int bid = blockIdx.x;
    int prefix = (bid == 0) ? 0 : ss2[bid - 1];
    int i = bid * SCAN_T + tid;
    int v = (i < N) ? g_degcnt[i] : 0;
    ss[tid] = v;
    __syncthreads();
#pragma unroll
    for (int off = 1; off < SCAN_T; off <<= 1) {
        int t = (tid >= off) ? ss[tid - off] : 0;
        __syncthreads();
        ss[tid] += t;
        __syncthreads();
    }
    if (i < N) {
        g_rowptr[i] = prefix + ss[tid] - v;
        float d = (float)v + 1.0f;
        g_dinv[i]  = rsqrtf(d);
        g_selfc[i] = 1.0f / d;
    }
    if (bid == nb - 1 && tid == SCAN_T - 1) g_rowptr[N] = ss2[nb - 1];
}

__global__ void k_fill(const void* __restrict__ ei, int E) {
    int e = blockIdx.x * blockDim.x + threadIdx.x;
    if (e < E) {
        int s = idx_at(ei, e);
        int d = idx_at(ei, E + e);
        int pos = g_rowptr[d] + atomicAdd(&g_cursor[d], 1);
        g_col[pos] = s;
    }
}

// ---------------- aggregation: one warp per node (max latency hiding) ----------------
template <typename VecT, bool FROM_GH>
__global__ void k_agg(const float* __restrict__ xin, int N) {
    int t = blockIdx.x * blockDim.x + threadIdx.x;
    int node = t >> 5;
    int lane = t & 31;
    if (node >= N) return;
    const VecT* __restrict__ xv = FROM_GH ? (const VecT*)g_h : (const VecT*)xin;
    VecT a = vscale(xv[node * 32 + lane], g_selfc[node]);
    float di = g_dinv[node];
    int p = g_rowptr[node];
    int e = g_rowptr[node + 1];
    for (; p + 4 <= e; p += 4) {
        int s0 = __ldg(&g_col[p]);
        int s1 = __ldg(&g_col[p + 1]);
        int s2 = __ldg(&g_col[p + 2]);
        int s3 = __ldg(&g_col[p + 3]);
        float w0 = di * __ldg(&g_dinv[s0]);
        float w1 = di * __ldg(&g_dinv[s1]);
        float w2 = di * __ldg(&g_dinv[s2]);
        float w3 = di * __ldg(&g_dinv[s3]);
        VecT v0 = xv[s0 * 32 + lane];
        VecT v1 = xv[s1 * 32 + lane];
        VecT v2 = xv[s2 * 32 + lane];
        VecT v3 = xv[s3 * 32 + lane];
        vfma(a, v0, w0);
        vfma(a, v1, w1);
        vfma(a, v2, w2);
        vfma(a, v3, w3);
    }
    for (; p < e; p++) {
        int s0 = __ldg(&g_col[p]);
        vfma(a, xv[s0 * 32 + lane], di * __ldg(&g_dinv[s0]));
    }
    ((VecT*)g_y)[node * 32 + lane] = a;
}

// ---------------- tensor-core GEMM via mma.sync (R12-proven) ----------------
// relu(g_y[N,K] @ W[K,128] + b). bf16x3: D = Ahi*Bhi + Ahi*Blo + Alo*Bhi.
// CTA 128x128, 8 warps (4x2), warp tile 32x64. K chunked by 32, smem pitch 40 bf16.
// POOL: pool bias+relu'd rows into g_psum (batch sorted) instead of writing g_h.
template <int K, bool POOL>
__global__ void __launch_bounds__(256) k_mma(const float* __restrict__ bias,
                                             const void* __restrict__ batch, int N) {
    __shared__ __align__(16) char smraw[40960];
    __nv_bfloat16* a_hi = (__nv_bfloat16*)(smraw);
    __nv_bfloat16* a_lo = (__nv_bfloat16*)(smraw + 10240);
    __nv_bfloat16* b_hi = (__nv_bfloat16*)(smraw + 20480);
    __nv_bfloat16* b_lo = (__nv_bfloat16*)(smraw + 30720);
    float* ps = (float*)smraw;   // [64][132] pool staging (POOL only)

    const int tid  = threadIdx.x;
    const int lane = tid & 31;
    const int wid  = tid >> 5;
    const int row0 = blockIdx.x * 128;
    const int mrow0 = (wid >> 1) * 32;
    const int ncol0 = (wid & 1) * 64;

    const __nv_bfloat16* whi = (K == 64) ? g_w1hi : g_w2hi;
    const __nv_bfloat16* wlo = (K == 64) ? g_w1lo : g_w2lo;

    float acc[2][8][4];
#pragma unroll
    for (int mt = 0; mt < 2; mt++)
#pragma unroll
        for (int nt = 0; nt < 8; nt++)
#pragma unroll
            for (int j = 0; j < 4; j++) acc[mt][nt][j] = 0.f;

    const unsigned a_hi_u = s2u(a_hi), a_lo_u = s2u(a_lo);
    const unsigned b_hi_u = s2u(b_hi), b_lo_u = s2u(b_lo);
    const int r = tid >> 1, half = tid & 1;

    for (int kc = 0; kc < K; kc += 32) {
        __syncthreads();
        // stage A: fp32 g_y -> bf16 hi/lo
        {
            int rowA = row0 + r;
            unsigned dsto = (unsigned)(r * 40 + half * 16) * 2;
            if (rowA < N) {
                const float4* src = (const float4*)(g_y + (size_t)rowA * K + kc + half * 16);
#pragma unroll
                for (int j = 0; j < 4; j++) {
                    float4 v = src[j];
                    unsigned h0, l0, h1, l1;
                    split2(v.x, v.y, h0, l0);
                    split2(v.z, v.w, h1, l1);
                    *(uint2*)((char*)a_hi + dsto + j * 8) = make_uint2(h0, h1);
                    *(uint2*)((char*)a_lo + dsto + j * 8) = make_uint2(l0, l1);
                }
            } else {
#pragma unroll
                for (int j = 0; j < 4; j++) {
                    *(uint2*)((char*)a_hi + dsto + j * 8) = make_uint2(0u, 0u);
                    *(uint2*)((char*)a_lo + dsto + j * 8) = make_uint2(0u, 0u);
                }
            }
        }
        // stage B: each thread covers 16 bf16 -> two uint4 loads
        {
            const uint4* sh = (const uint4*)(whi + (size_t)r * K + kc + half * 16);
            const uint4* sl = (const uint4*)(wlo + (size_t)r * K + kc + half * 16);
            unsigned dsto = (unsigned)(r * 40 + half * 16) * 2;
            *(uint4*)((char*)b_hi + dsto)      = sh[0];
            *(uint4*)((char*)b_hi + dsto + 16) = sh[1];
            *(uint4*)((char*)b_lo + dsto)      = sl[0];
            *(uint4*)((char*)b_lo + dsto + 16) = sl[1];
        }
        __syncthreads();

        const int lr = lane & 15, lc = lane >> 4;
#pragma unroll
        for (int ks = 0; ks < 32; ks += 16) {
            unsigned ah[2][4], al[2][4];
#pragma unroll
            for (int mt = 0; mt < 2; mt++) {
                unsigned ao = (unsigned)((mrow0 + mt * 16 + lr) * 40 + ks + lc * 8) * 2;
                LDM4(ah[mt], a_hi_u + ao);
                LDM4(al[mt], a_lo_u + ao);
            }
#pragma unroll
            for (int np = 0; np < 4; np++) {
                unsigned bo = (unsigned)((ncol0 + np * 16 + lr) * 40 + ks + lc * 8) * 2;
                unsigned bh[4], bl[4];
                LDM4(bh, b_hi_u + bo);
                LDM4(bl, b_lo_u + bo);
#pragma unroll
                for (int sub = 0; sub < 2; sub++) {
                    int nt = 2 * np + sub;
#pragma unroll
                    for (int mt = 0; mt < 2; mt++) {
                        MMA_BF16(acc[mt][nt], ah[mt], bh[sub], bh[sub + 2]);
                        MMA_BF16(acc[mt][nt], ah[mt], bl[sub], bl[sub + 2]);
                        MMA_BF16(acc[mt][nt], al[mt], bh[sub], bh[sub + 2]);
                    }
                }
            }
        }
    }

    const int tq  = lane >> 2;
    const int tc2 = (lane & 3) * 2;

    if (!POOL) {
#pragma unroll
        for (int mt = 0; mt < 2; mt++) {
            int rowa = row0 + mrow0 + mt * 16 + tq;
            int rowb = rowa + 8;
#pragma unroll
            for (int nt = 0; nt < 8; nt++) {
                int col = ncol0 + nt * 8 + tc2;
                float b0 = __ldg(&bias[col]), b1 = __ldg(&bias[col + 1]);
                const float* c = acc[mt][nt];
                if (rowa < N)
                    *(float2*)(g_h + (size_t)rowa * 128 + col) =
                        make_float2(fmaxf(c[0] + b0, 0.f), fmaxf(c[1] + b1, 0.f));
                if (rowb < N)
                    *(float2*)(g_h + (size_t)rowb * 128 + col) =
                        make_float2(fmaxf(c[2] + b0, 0.f), fmaxf(c[3] + b1, 0.f));
            }
        }
    } else {
#pragma unroll
        for (int P = 0; P < 2; P++) {
            __syncthreads();
            if ((mrow0 >> 6) == P) {
                int baseR = mrow0 & 63;
#pragma unroll
                for (int mt = 0; mt < 2; mt++) {
                    int ra = baseR + mt * 16 + tq;
                    int rb = ra + 8;
#pragma unroll
                    for (int nt = 0; nt < 8; nt++) {
                        int col = ncol0 + nt * 8 + tc2;
                        float b0 = __ldg(&bias[col]), b1 = __ldg(&bias[col + 1]);
                        const float* c = acc[mt][nt];
                        ps[ra * 132 + col]     = fmaxf(c[0] + b0, 0.f);
                        ps[ra * 132 + col + 1] = fmaxf(c[1] + b1, 0.f);
                        ps[rb * 132 + col]     = fmaxf(c[2] + b0, 0.f);
                        ps[rb * 132 + col + 1] = fmaxf(c[3] + b1, 0.f);
                    }
                }
            }
            __syncthreads();
            int c  = tid & 127;
            int rh = tid >> 7;
            int curg = -1;
            float acc2 = 0.f;
            for (int rr = rh * 32; rr < rh * 32 + 32; rr++) {
                int row = row0 + P * 64 + rr;
                if (row >= N) break;
                int g = idx_at(batch, row);
                if (g != curg) {
                    if (curg >= 0) atomicAdd(&g_psum[curg * 128 + c], acc2);
                    curg = g; acc2 = 0.f;
                }
                acc2 += ps[rr * 132 + c];
            }
            if (curg >= 0) atomicAdd(&g_psum[curg * 128 + c], acc2);
        }
    }
}

// ---------------- final FC (128 -> 2) + softmax ----------------
__global__ void k_fc(const float* __restrict__ Wfc, const float* __restrict__ bfc,
                     float* __restrict__ out, int G) {
    int g = blockIdx.x * blockDim.x + threadIdx.x;
    if (g >= G) return;
    float inv = 1.0f / fmaxf(g_gcnt[g], 1.0f);
    float l0 = bfc[0], l1 = bfc[1];
#pragma unroll 8
    for (int c = 0; c < 128; c++) {
        float p = g_psum[g * 128 + c] * inv;
        l0 = fmaf(p, Wfc[2 * c + 0], l0);
        l1 = fmaf(p, Wfc[2 * c + 1], l1);
    }
    float m = fmaxf(l0, l1);
    float e0 = __expf(l0 - m), e1 = __expf(l1 - m);
    float s = e0 + e1;
    out[2 * g + 0] = e0 / s;
    out[2 * g + 1] = e1 / s;
}

// ---------------- launch: ONLY kernel launches ----------------
extern "C" void kernel_launch(void* const* d_in, const int* in_sizes, int n_in,
                              void* d_out, int out_size) {
    const float* x     = (const float*)d_in[0];
    const void*  ei    = d_in[1];
    const void*  batch = d_in[2];

    const float *W1 = 0, *b1 = 0, *W2 = 0, *b2 = 0, *Wfc = 0, *bfc = 0;
    for (int i = 3; i < n_in; i++) {
        int s = in_sizes[i];
        const float* p = (const float*)d_in[i];
        if      (s == 8192)  W1 = p;
        else if (s == 16384) W2 = p;
        else if (s == 256)   Wfc = p;
        else if (s == 2)     bfc = p;
        else if (s == 128)   { if (!b1) b1 = p; else b2 = p; }
    }

    int N = in_sizes[2];
    int E = in_sizes[1] / 2;
    int G = out_size / 2;

    k_setup<<<256, 256>>>((const unsigned*)ei, W1, W2, G);
    k_zero<<<(N + 255) / 256, 256>>>(batch, N);
    k_count<<<(E + 255) / 256, 256>>>(ei, E);
    int nb = (N + SCAN_T - 1) / SCAN_T;
    k_scan1<<<nb, SCAN_T>>>(N);
    k_scan23<<<nb, SCAN_T>>>(nb, N);
    k_fill<<<(E + 255) / 256, 256>>>(ei, E);

    int aggBlocks = (N * 32 + 255) / 256;
    int mmaBlocks = (N + 127) / 128;

    // layer 1: g_y = A_hat x (N x 64); g_h = relu(g_y W1 + b1)
    k_agg<float2, false><<<aggBlocks, 256>>>(x, N);
    k_mma<64, false><<<mmaBlocks, 256>>>(b1, batch, N);

    // layer 2: g_y = A_hat g_h (N x 128); pooled relu(g_y W2 + b2) -> g_psum
    k_agg<float4, true><<<aggBlocks, 256>>>(nullptr, N);
    k_mma<128, true><<<mmaBlocks, 256>>>(b2, batch, N);

    // FC + softmax
    k_fc<<<(G + 127) / 128, 128>>>(Wfc, bfc, (float*)d_out, G);
}